// round 1
// baseline (speedup 1.0000x reference)
#include <cuda_runtime.h>
#include <math.h>

// Problem constants
#define Bq   2
#define Hq   8
#define Nq   2048
#define Mq   2048
#define DIMq 512
#define DHq  64
#define INNERq 512   // Hq*DHq

// Device scratch (no cudaMalloc allowed)
__device__ float g_Q[Bq * Hq * Nq * DHq];      // [b,h,n,d]
__device__ float g_K[Bq * Hq * Mq * DHq];      // [b,h,m,d]
__device__ float g_V[Bq * Hq * Nq * DHq];      // [b,h,m,d]  (v uses m == n here)
__device__ float g_O[Bq * Nq * INNERq];        // [b,n,h*d]

// ---------------------------------------------------------------------------
// Generic 64x64 fp32 GEMM tile accumulator: C_tile += A[row0:row0+64, :K] * B[:K, col0:col0+64]
// A row-major (lda), B row-major (ldb). 256 threads, each computes 4x4.
// ---------------------------------------------------------------------------
__device__ __forceinline__ void gemm64_acc(const float* __restrict__ A, int lda,
                                           const float* __restrict__ B, int ldb,
                                           int row0, int col0, int K,
                                           float acc[4][4],
                                           float* sA /*16x68 (k-major)*/,
                                           float* sB /*16x64*/) {
    const int tid = threadIdx.x;
    const int tx = tid & 15;
    const int ty = tid >> 4;

    for (int k0 = 0; k0 < K; k0 += 16) {
        __syncthreads();
        // Load A tile (64 rows x 16 k), store transposed: sA[k][m], stride 68
        {
            int r  = tid >> 2;          // 0..63
            int kc = (tid & 3) * 4;     // 0,4,8,12
            float4 a = *(const float4*)&A[(size_t)(row0 + r) * lda + k0 + kc];
            sA[(kc + 0) * 68 + r] = a.x;
            sA[(kc + 1) * 68 + r] = a.y;
            sA[(kc + 2) * 68 + r] = a.z;
            sA[(kc + 3) * 68 + r] = a.w;
        }
        // Load B tile (16 k x 64 cols): sB[k][n], stride 64
        {
            int r  = tid >> 4;          // 0..15
            int c4 = (tid & 15) * 4;    // 0..60
            *(float4*)&sB[r * 64 + c4] =
                *(const float4*)&B[(size_t)(k0 + r) * ldb + col0 + c4];
        }
        __syncthreads();

#pragma unroll
        for (int k = 0; k < 16; k++) {
            float4 a = *(float4*)&sA[k * 68 + ty * 4];
            float4 b = *(float4*)&sB[k * 64 + tx * 4];
            acc[0][0] += a.x * b.x; acc[0][1] += a.x * b.y; acc[0][2] += a.x * b.z; acc[0][3] += a.x * b.w;
            acc[1][0] += a.y * b.x; acc[1][1] += a.y * b.y; acc[1][2] += a.y * b.z; acc[1][3] += a.y * b.w;
            acc[2][0] += a.z * b.x; acc[2][1] += a.z * b.y; acc[2][2] += a.z * b.z; acc[2][3] += a.z * b.w;
            acc[3][0] += a.w * b.x; acc[3][1] += a.w * b.y; acc[3][2] += a.w * b.z; acc[3][3] += a.w * b.w;
        }
    }
}

// ---------------------------------------------------------------------------
// Kernel 1: QV projection.  x[4096,512] @ W_qv[512,1024] -> Q,V in head layout
// ---------------------------------------------------------------------------
__global__ void __launch_bounds__(256) proj_qv_kernel(const float* __restrict__ x,
                                                      const float* __restrict__ Wqv) {
    __shared__ float sA[16 * 68];
    __shared__ float sB[16 * 64];
    float acc[4][4] = {};
    const int row0 = blockIdx.y * 64;
    const int col0 = blockIdx.x * 64;
    gemm64_acc(x, DIMq, Wqv, 2 * INNERq, row0, col0, DIMq, acc, sA, sB);

    const int tx = threadIdx.x & 15;
    const int ty = threadIdx.x >> 4;
#pragma unroll
    for (int i = 0; i < 4; i++) {
#pragma unroll
        for (int j = 0; j < 4; j++) {
            int r = row0 + ty * 4 + i;          // global row in [0,4096)
            int c = col0 + tx * 4 + j;          // global col in [0,1024)
            int b = r >> 11, n = r & 2047;
            if (c < INNERq) {
                int h = c >> 6, d = c & 63;
                g_Q[(((size_t)(b * Hq + h)) * Nq + n) * DHq + d] = acc[i][j];
            } else {
                int cc = c - INNERq;
                int h = cc >> 6, d = cc & 63;
                g_V[(((size_t)(b * Hq + h)) * Nq + n) * DHq + d] = acc[i][j];
            }
        }
    }
}

// ---------------------------------------------------------------------------
// Kernel 2: K projection.  x1[4096,512] @ W_k[512,512] -> K head layout
// ---------------------------------------------------------------------------
__global__ void __launch_bounds__(256) proj_k_kernel(const float* __restrict__ x1,
                                                     const float* __restrict__ Wk) {
    __shared__ float sA[16 * 68];
    __shared__ float sB[16 * 64];
    float acc[4][4] = {};
    const int row0 = blockIdx.y * 64;
    const int col0 = blockIdx.x * 64;
    gemm64_acc(x1, DIMq, Wk, INNERq, row0, col0, DIMq, acc, sA, sB);

    const int tx = threadIdx.x & 15;
    const int ty = threadIdx.x >> 4;
#pragma unroll
    for (int i = 0; i < 4; i++) {
#pragma unroll
        for (int j = 0; j < 4; j++) {
            int r = row0 + ty * 4 + i;
            int c = col0 + tx * 4 + j;
            int b = r >> 11, m = r & 2047;
            int h = c >> 6, d = c & 63;
            g_K[(((size_t)(b * Hq + h)) * Mq + m) * DHq + d] = acc[i][j];
        }
    }
}

// ---------------------------------------------------------------------------
// Kernel 3: fused flash attention per (b, h, 64-row tile).
// dots = (q.k)*scale*dots_para + attn_mat*mat_para ; softmax ; O = P@V
// Smem: Qs[64][64] | KVs[64][68] | Ps[64][64]  (dynamic, 50176 B)
// ---------------------------------------------------------------------------
#define ATTN_SMEM_FLOATS (64 * 64 + 64 * 68 + 64 * 64)
#define ATTN_SMEM_BYTES  (ATTN_SMEM_FLOATS * 4)

__global__ void __launch_bounds__(256) attn_kernel(const float* __restrict__ attn_mat,
                                                   const float* __restrict__ dots_para,
                                                   const float* __restrict__ mat_para) {
    extern __shared__ float sm[];
    float* Qs  = sm;                       // stride 64
    float* KVs = sm + 64 * 64;             // stride 68 (K then V)
    float* Ps  = sm + 64 * 64 + 64 * 68;   // stride 64

    const int b  = blockIdx.z;
    const int h  = blockIdx.y;
    const int n0 = blockIdx.x * 64;
    const int tid = threadIdx.x;
    const int tx = tid & 15;
    const int ty = tid >> 4;
    const int r0 = ty * 4;
    const int c0 = tx * 4;
    const size_t bh = (size_t)(b * Hq + h);

    const float dp = __ldg(dots_para) * 0.125f;   // scale = DH^-0.5 = 0.125
    const float mp = __ldg(mat_para);

    // Load Q tile once
    const float* Qg = g_Q + (bh * Nq + n0) * DHq;
#pragma unroll
    for (int it = 0; it < 4; it++) {
        int f = tid + it * 256;            // float4 index 0..1023
        int rr = f >> 4, dd = (f & 15) * 4;
        *(float4*)&Qs[rr * 64 + dd] = *(const float4*)&Qg[rr * 64 + dd];
    }

    float acc[4][4] = {};
    float mi[4], li[4];
#pragma unroll
    for (int i = 0; i < 4; i++) { mi[i] = -1e30f; li[i] = 0.0f; }

    const float* Amg = attn_mat + (bh * Nq + n0) * (size_t)Mq;

    for (int ch = 0; ch < 32; ch++) {
        const int m0 = ch * 64;
        __syncthreads();   // KVs free (prev PV done), Qs visible on first iter

        // Load K chunk: KVs[m][d], stride 68
        const float* Kg = g_K + (bh * Mq + m0) * DHq;
#pragma unroll
        for (int it = 0; it < 4; it++) {
            int f = tid + it * 256;
            int mm = f >> 4, dd = (f & 15) * 4;
            *(float4*)&KVs[mm * 68 + dd] = *(const float4*)&Kg[mm * 64 + dd];
        }
        __syncthreads();

        // S = Q K^T for this 64x64 tile
        float s[4][4] = {};
#pragma unroll
        for (int d = 0; d < 64; d += 4) {
            float4 q0 = *(float4*)&Qs[(r0 + 0) * 64 + d];
            float4 q1 = *(float4*)&Qs[(r0 + 1) * 64 + d];
            float4 q2 = *(float4*)&Qs[(r0 + 2) * 64 + d];
            float4 q3 = *(float4*)&Qs[(r0 + 3) * 64 + d];
#pragma unroll
            for (int j = 0; j < 4; j++) {
                float4 k = *(float4*)&KVs[(c0 + j) * 68 + d];
                s[0][j] += q0.x * k.x + q0.y * k.y + q0.z * k.z + q0.w * k.w;
                s[1][j] += q1.x * k.x + q1.y * k.y + q1.z * k.z + q1.w * k.w;
                s[2][j] += q2.x * k.x + q2.y * k.y + q2.z * k.z + q2.w * k.w;
                s[3][j] += q3.x * k.x + q3.y * k.y + q3.z * k.z + q3.w * k.w;
            }
        }

        // scale + bias, online softmax
#pragma unroll
        for (int i = 0; i < 4; i++) {
            float4 am = __ldg((const float4*)&Amg[(size_t)(r0 + i) * Mq + m0 + c0]);
            s[i][0] = s[i][0] * dp + mp * am.x;
            s[i][1] = s[i][1] * dp + mp * am.y;
            s[i][2] = s[i][2] * dp + mp * am.z;
            s[i][3] = s[i][3] * dp + mp * am.w;

            float rm = fmaxf(fmaxf(s[i][0], s[i][1]), fmaxf(s[i][2], s[i][3]));
#pragma unroll
            for (int o = 8; o >= 1; o >>= 1)
                rm = fmaxf(rm, __shfl_xor_sync(0xffffffffu, rm, o));
            float mnew = fmaxf(mi[i], rm);
            float cor = __expf(mi[i] - mnew);
            mi[i] = mnew;

            float rs = 0.0f;
#pragma unroll
            for (int j = 0; j < 4; j++) {
                s[i][j] = __expf(s[i][j] - mnew);
                rs += s[i][j];
            }
#pragma unroll
            for (int o = 8; o >= 1; o >>= 1)
                rs += __shfl_xor_sync(0xffffffffu, rs, o);
            li[i] = li[i] * cor + rs;
#pragma unroll
            for (int j = 0; j < 4; j++) acc[i][j] *= cor;

            // store P row segment
            *(float4*)&Ps[(r0 + i) * 64 + c0] = make_float4(s[i][0], s[i][1], s[i][2], s[i][3]);
        }
        __syncthreads();   // P visible; all K reads done -> KVs reusable

        // Load V chunk into KVs
        const float* Vg = g_V + (bh * Mq + m0) * DHq;
#pragma unroll
        for (int it = 0; it < 4; it++) {
            int f = tid + it * 256;
            int mm = f >> 4, dd = (f & 15) * 4;
            *(float4*)&KVs[mm * 68 + dd] = *(const float4*)&Vg[mm * 64 + dd];
        }
        __syncthreads();

        // acc += P @ V   (O cols = head dims, thread owns d = c0..c0+3)
#pragma unroll 8
        for (int m = 0; m < 64; m++) {
            float4 v = *(float4*)&KVs[m * 68 + c0];
            float p0 = Ps[(r0 + 0) * 64 + m];
            float p1 = Ps[(r0 + 1) * 64 + m];
            float p2 = Ps[(r0 + 2) * 64 + m];
            float p3 = Ps[(r0 + 3) * 64 + m];
            acc[0][0] += p0 * v.x; acc[0][1] += p0 * v.y; acc[0][2] += p0 * v.z; acc[0][3] += p0 * v.w;
            acc[1][0] += p1 * v.x; acc[1][1] += p1 * v.y; acc[1][2] += p1 * v.z; acc[1][3] += p1 * v.w;
            acc[2][0] += p2 * v.x; acc[2][1] += p2 * v.y; acc[2][2] += p2 * v.z; acc[2][3] += p2 * v.w;
            acc[3][0] += p3 * v.x; acc[3][1] += p3 * v.y; acc[3][2] += p3 * v.z; acc[3][3] += p3 * v.w;
        }
    }

    // Epilogue: normalize and write to [b, n, h*64 + d]
    float* Og = g_O + ((size_t)(b * Nq + n0)) * INNERq + h * DHq;
#pragma unroll
    for (int i = 0; i < 4; i++) {
        float inv = 1.0f / li[i];
        float4 o;
        o.x = acc[i][0] * inv; o.y = acc[i][1] * inv;
        o.z = acc[i][2] * inv; o.w = acc[i][3] * inv;
        *(float4*)&Og[(size_t)(r0 + i) * INNERq + c0] = o;
    }
}

// ---------------------------------------------------------------------------
// Kernel 4: output projection.  g_O[4096,512] @ W_out[512,512] + b_out -> d_out
// ---------------------------------------------------------------------------
__global__ void __launch_bounds__(256) out_proj_kernel(const float* __restrict__ Wout,
                                                       const float* __restrict__ bout,
                                                       float* __restrict__ out) {
    __shared__ float sA[16 * 68];
    __shared__ float sB[16 * 64];
    float acc[4][4] = {};
    const int row0 = blockIdx.y * 64;
    const int col0 = blockIdx.x * 64;
    gemm64_acc(g_O, INNERq, Wout, DIMq, row0, col0, INNERq, acc, sA, sB);

    const int tx = threadIdx.x & 15;
    const int ty = threadIdx.x >> 4;
#pragma unroll
    for (int i = 0; i < 4; i++) {
        int r = row0 + ty * 4 + i;
        int c = col0 + tx * 4;
        float4 bb = *(const float4*)&bout[c];
        float4 o;
        o.x = acc[i][0] + bb.x;
        o.y = acc[i][1] + bb.y;
        o.z = acc[i][2] + bb.z;
        o.w = acc[i][3] + bb.w;
        *(float4*)&out[(size_t)r * DIMq + c] = o;
    }
}

// ---------------------------------------------------------------------------
extern "C" void kernel_launch(void* const* d_in, const int* in_sizes, int n_in,
                              void* d_out, int out_size) {
    const float* x    = (const float*)d_in[0];
    const float* x1   = (const float*)d_in[1];
    const float* am   = (const float*)d_in[2];
    const float* dp   = (const float*)d_in[3];
    const float* mp   = (const float*)d_in[4];
    const float* Wqv  = (const float*)d_in[5];
    const float* Wk   = (const float*)d_in[6];
    const float* Wout = (const float*)d_in[7];
    const float* bout = (const float*)d_in[8];
    float* out = (float*)d_out;

    cudaFuncSetAttribute(attn_kernel, cudaFuncAttributeMaxDynamicSharedMemorySize,
                         ATTN_SMEM_BYTES);

    proj_qv_kernel<<<dim3(2 * INNERq / 64, (Bq * Nq) / 64), 256>>>(x, Wqv);
    proj_k_kernel<<<dim3(INNERq / 64, (Bq * Mq) / 64), 256>>>(x1, Wk);
    attn_kernel<<<dim3(Nq / 64, Hq, Bq), 256, ATTN_SMEM_BYTES>>>(am, dp, mp);
    out_proj_kernel<<<dim3(DIMq / 64, (Bq * Nq) / 64), 256>>>(Wout, bout, out);
}

// round 2
// speedup vs baseline: 3.2320x; 3.2320x over previous
#include <cuda_runtime.h>
#include <math.h>

// Problem constants
#define Bq   2
#define Hq   8
#define Nq   2048
#define Mq   2048
#define DIMq 512
#define DHq  64
#define INNERq 512   // Hq*DHq

// Device scratch (no cudaMalloc allowed)
__device__ float g_Q[Bq * Hq * Nq * DHq];      // [b,h,n,d]
__device__ float g_K[Bq * Hq * Mq * DHq];      // [b,h,m,d]
__device__ float g_V[Bq * Hq * Nq * DHq];      // [b,h,m,d]
__device__ float g_O[Bq * Nq * INNERq];        // [b,n,h*d]

// ---------------------------------------------------------------------------
// TF32 helpers
// ---------------------------------------------------------------------------
__device__ __forceinline__ float tf32r(float x) {
    unsigned u;
    asm("cvt.rna.tf32.f32 %0, %1;" : "=r"(u) : "f"(x));
    return __uint_as_float(u);
}
#define FU(x) __float_as_uint(x)

__device__ __forceinline__ void mma8(float& c0, float& c1, float& c2, float& c3,
                                     unsigned a0, unsigned a1, unsigned a2, unsigned a3,
                                     unsigned b0, unsigned b1) {
    asm volatile(
        "mma.sync.aligned.m16n8k8.row.col.f32.tf32.tf32.f32 "
        "{%0,%1,%2,%3}, {%4,%5,%6,%7}, {%8,%9}, {%0,%1,%2,%3};\n"
        : "+f"(c0), "+f"(c1), "+f"(c2), "+f"(c3)
        : "r"(a0), "r"(a1), "r"(a2), "r"(a3), "r"(b0), "r"(b1));
}

// ---------------------------------------------------------------------------
// 128x128 tf32 GEMM core. 256 threads = 8 warps (2x4). Warp tile 64x32.
// sA: [128][20] (row-major, stride 20), sB: [16][136] (row-major, stride 136)
// c[mt*4+nt][0..3] = C fragments for 16 m16n8 tiles.
// ---------------------------------------------------------------------------
__device__ __forceinline__ void gemm128_tf32(const float* __restrict__ A, int lda,
                                             const float* __restrict__ B, int ldb,
                                             int row0, int col0, int K,
                                             float c[16][4],
                                             float* sA, float* sB) {
    const int tid  = threadIdx.x;
    const int lane = tid & 31;
    const int w    = tid >> 5;
    const int wm   = w >> 2;   // 0..1
    const int wn   = w & 3;    // 0..3
    const int g    = lane >> 2;
    const int t    = lane & 3;

    for (int ko = 0; ko < K; ko += 16) {
        __syncthreads();
        // Load A tile 128x16 (tf32-rounded)
#pragma unroll
        for (int i = 0; i < 2; i++) {
            int f  = tid + i * 256;       // 0..511 float4s
            int r  = f >> 2;
            int c4 = (f & 3) * 4;
            float4 v = *(const float4*)&A[(size_t)(row0 + r) * lda + ko + c4];
            v.x = tf32r(v.x); v.y = tf32r(v.y); v.z = tf32r(v.z); v.w = tf32r(v.w);
            *(float4*)&sA[r * 20 + c4] = v;
        }
        // Load B tile 16x128
#pragma unroll
        for (int i = 0; i < 2; i++) {
            int f  = tid + i * 256;
            int r  = f >> 5;
            int c4 = (f & 31) * 4;
            float4 v = *(const float4*)&B[(size_t)(ko + r) * ldb + col0 + c4];
            v.x = tf32r(v.x); v.y = tf32r(v.y); v.z = tf32r(v.z); v.w = tf32r(v.w);
            *(float4*)&sB[r * 136 + c4] = v;
        }
        __syncthreads();

#pragma unroll
        for (int kk = 0; kk < 16; kk += 8) {
            unsigned a[4][4], b[4][2];
#pragma unroll
            for (int mt = 0; mt < 4; mt++) {
                int rl = (wm * 64 + mt * 16 + g) * 20;
                int rh = rl + 8 * 20;
                a[mt][0] = FU(sA[rl + kk + t]);
                a[mt][1] = FU(sA[rh + kk + t]);
                a[mt][2] = FU(sA[rl + kk + t + 4]);
                a[mt][3] = FU(sA[rh + kk + t + 4]);
            }
#pragma unroll
            for (int nt = 0; nt < 4; nt++) {
                int cc = wn * 32 + nt * 8 + g;
                b[nt][0] = FU(sB[(kk + t) * 136 + cc]);
                b[nt][1] = FU(sB[(kk + t + 4) * 136 + cc]);
            }
#pragma unroll
            for (int mt = 0; mt < 4; mt++)
#pragma unroll
                for (int nt = 0; nt < 4; nt++)
                    mma8(c[mt * 4 + nt][0], c[mt * 4 + nt][1],
                         c[mt * 4 + nt][2], c[mt * 4 + nt][3],
                         a[mt][0], a[mt][1], a[mt][2], a[mt][3],
                         b[nt][0], b[nt][1]);
        }
    }
}

// ---------------------------------------------------------------------------
// Kernel 1: QV projection.  x[4096,512] @ W_qv[512,1024] -> Q,V head layout
// ---------------------------------------------------------------------------
__global__ void __launch_bounds__(256) proj_qv_kernel(const float* __restrict__ x,
                                                      const float* __restrict__ Wqv) {
    __shared__ float sA[128 * 20];
    __shared__ float sB[16 * 136];
    float c[16][4] = {};
    const int row0 = blockIdx.y * 128;
    const int col0 = blockIdx.x * 128;
    gemm128_tf32(x, DIMq, Wqv, 2 * INNERq, row0, col0, DIMq, c, sA, sB);

    const int tid  = threadIdx.x;
    const int lane = tid & 31;
    const int w    = tid >> 5;
    const int wm   = w >> 2, wn = w & 3;
    const int g    = lane >> 2, t = lane & 3;
    const bool isV = (col0 >= INNERq);
    float* dst = isV ? g_V : g_Q;

#pragma unroll
    for (int mt = 0; mt < 4; mt++) {
#pragma unroll
        for (int nt = 0; nt < 4; nt++) {
            int r  = row0 + wm * 64 + mt * 16 + g;
            int cc = col0 + wn * 32 + nt * 8 + 2 * t;
            int b  = r >> 11, n = r & 2047;
            int colq = isV ? cc - INNERq : cc;
            int h = colq >> 6, d = colq & 63;
            size_t base = (((size_t)(b * Hq + h)) * Nq + n) * DHq + d;
            float2 lo = make_float2(c[mt * 4 + nt][0], c[mt * 4 + nt][1]);
            float2 hi = make_float2(c[mt * 4 + nt][2], c[mt * 4 + nt][3]);
            *(float2*)&dst[base]            = lo;
            *(float2*)&dst[base + 8 * DHq]  = hi;   // row+8, same (b,h)
        }
    }
}

// ---------------------------------------------------------------------------
// Kernel 2: K projection.  x1[4096,512] @ W_k[512,512] -> K head layout
// ---------------------------------------------------------------------------
__global__ void __launch_bounds__(256) proj_k_kernel(const float* __restrict__ x1,
                                                     const float* __restrict__ Wk) {
    __shared__ float sA[128 * 20];
    __shared__ float sB[16 * 136];
    float c[16][4] = {};
    const int row0 = blockIdx.y * 128;
    const int col0 = blockIdx.x * 128;
    gemm128_tf32(x1, DIMq, Wk, INNERq, row0, col0, DIMq, c, sA, sB);

    const int tid  = threadIdx.x;
    const int lane = tid & 31;
    const int w    = tid >> 5;
    const int wm   = w >> 2, wn = w & 3;
    const int g    = lane >> 2, t = lane & 3;

#pragma unroll
    for (int mt = 0; mt < 4; mt++) {
#pragma unroll
        for (int nt = 0; nt < 4; nt++) {
            int r  = row0 + wm * 64 + mt * 16 + g;
            int cc = col0 + wn * 32 + nt * 8 + 2 * t;
            int b  = r >> 11, m = r & 2047;
            int h = cc >> 6, d = cc & 63;
            size_t base = (((size_t)(b * Hq + h)) * Mq + m) * DHq + d;
            *(float2*)&g_K[base]           = make_float2(c[mt * 4 + nt][0], c[mt * 4 + nt][1]);
            *(float2*)&g_K[base + 8 * DHq] = make_float2(c[mt * 4 + nt][2], c[mt * 4 + nt][3]);
        }
    }
}

// ---------------------------------------------------------------------------
// Kernel 3: fused flash attention, tf32 mma. 128 threads = 4 warps.
// Block = (b, h, 64 Q rows). Warp w owns rows w*16..w*16+15.
// Smem: QPs[64][72] (Q then reused as P), Ks[64][72], Vs[64][72]
// ---------------------------------------------------------------------------
#define ATTN_SMEM_BYTES (3 * 64 * 72 * 4)

__global__ void __launch_bounds__(128) attn_kernel(const float* __restrict__ attn_mat,
                                                   const float* __restrict__ dots_para,
                                                   const float* __restrict__ mat_para) {
    extern __shared__ float sm[];
    float* QPs = sm;              // 64x72
    float* Ks  = sm + 64 * 72;
    float* Vs  = sm + 2 * 64 * 72;

    const int tid  = threadIdx.x;
    const int lane = tid & 31;
    const int w    = tid >> 5;
    const int g    = lane >> 2;
    const int t    = lane & 3;
    const int b    = blockIdx.z;
    const int h    = blockIdx.y;
    const int n0   = blockIdx.x * 64;
    const size_t bh = (size_t)(b * Hq + h);

    const float dp = __ldg(dots_para) * 0.125f;  // scale = DH^-0.5
    const float mp = __ldg(mat_para);

    // Load Q tile into smem (tf32)
    const float* Qg = g_Q + (bh * Nq + n0) * DHq;
#pragma unroll
    for (int i = 0; i < 8; i++) {
        int f = tid + i * 128;
        int r = f >> 4, c4 = (f & 15) * 4;
        float4 v = *(const float4*)&Qg[r * 64 + c4];
        v.x = tf32r(v.x); v.y = tf32r(v.y); v.z = tf32r(v.z); v.w = tf32r(v.w);
        *(float4*)&QPs[r * 72 + c4] = v;
    }
    __syncthreads();

    // Q fragments to registers (warp-private rows)
    unsigned qa[8][4];
    {
        int rl = (w * 16 + g) * 72;
        int rh = rl + 8 * 72;
#pragma unroll
        for (int k8 = 0; k8 < 8; k8++) {
            qa[k8][0] = FU(QPs[rl + k8 * 8 + t]);
            qa[k8][1] = FU(QPs[rh + k8 * 8 + t]);
            qa[k8][2] = FU(QPs[rl + k8 * 8 + t + 4]);
            qa[k8][3] = FU(QPs[rh + k8 * 8 + t + 4]);
        }
    }

    float o[8][4] = {};
    float mrow0 = -1e30f, mrow1 = -1e30f, lrow0 = 0.0f, lrow1 = 0.0f;

    for (int ch = 0; ch < 32; ch++) {
        const int m0 = ch * 64;
        __syncthreads();   // previous chunk's Ks/Vs reads complete

        const float* Kg = g_K + (bh * Mq + m0) * DHq;
        const float* Vg = g_V + (bh * Mq + m0) * DHq;
#pragma unroll
        for (int i = 0; i < 8; i++) {
            int f = tid + i * 128;
            int r = f >> 4, c4 = (f & 15) * 4;
            float4 v = *(const float4*)&Kg[r * 64 + c4];
            v.x = tf32r(v.x); v.y = tf32r(v.y); v.z = tf32r(v.z); v.w = tf32r(v.w);
            *(float4*)&Ks[r * 72 + c4] = v;
            float4 u = *(const float4*)&Vg[r * 64 + c4];
            u.x = tf32r(u.x); u.y = tf32r(u.y); u.z = tf32r(u.z); u.w = tf32r(u.w);
            *(float4*)&Vs[r * 72 + c4] = u;
        }
        __syncthreads();

        // S = Q K^T  (warp: 16 rows x 64 cols)
        float s[8][4] = {};
#pragma unroll
        for (int k8 = 0; k8 < 8; k8++) {
#pragma unroll
            for (int nt = 0; nt < 8; nt++) {
                int cb = (nt * 8 + g) * 72 + k8 * 8 + t;
                unsigned b0 = FU(Ks[cb]);
                unsigned b1 = FU(Ks[cb + 4]);
                mma8(s[nt][0], s[nt][1], s[nt][2], s[nt][3],
                     qa[k8][0], qa[k8][1], qa[k8][2], qa[k8][3], b0, b1);
            }
        }

        // scale + bias + online softmax (thread owns rows g and g+8 of warp tile)
        const float* Am = attn_mat + (bh * Nq + (n0 + w * 16 + g)) * (size_t)Mq + m0;
        float mx0 = -1e30f, mx1 = -1e30f;
#pragma unroll
        for (int nt = 0; nt < 8; nt++) {
            float2 alo = __ldg((const float2*)&Am[nt * 8 + 2 * t]);
            float2 ahi = __ldg((const float2*)&Am[(size_t)8 * Mq + nt * 8 + 2 * t]);
            s[nt][0] = s[nt][0] * dp + mp * alo.x;
            s[nt][1] = s[nt][1] * dp + mp * alo.y;
            s[nt][2] = s[nt][2] * dp + mp * ahi.x;
            s[nt][3] = s[nt][3] * dp + mp * ahi.y;
            mx0 = fmaxf(mx0, fmaxf(s[nt][0], s[nt][1]));
            mx1 = fmaxf(mx1, fmaxf(s[nt][2], s[nt][3]));
        }
        mx0 = fmaxf(mx0, __shfl_xor_sync(0xffffffffu, mx0, 1));
        mx0 = fmaxf(mx0, __shfl_xor_sync(0xffffffffu, mx0, 2));
        mx1 = fmaxf(mx1, __shfl_xor_sync(0xffffffffu, mx1, 1));
        mx1 = fmaxf(mx1, __shfl_xor_sync(0xffffffffu, mx1, 2));

        float mn0 = fmaxf(mrow0, mx0), mn1 = fmaxf(mrow1, mx1);
        float cor0 = __expf(mrow0 - mn0), cor1 = __expf(mrow1 - mn1);
        mrow0 = mn0; mrow1 = mn1;

        float rs0 = 0.0f, rs1 = 0.0f;
#pragma unroll
        for (int nt = 0; nt < 8; nt++) {
            s[nt][0] = __expf(s[nt][0] - mn0); rs0 += s[nt][0];
            s[nt][1] = __expf(s[nt][1] - mn0); rs0 += s[nt][1];
            s[nt][2] = __expf(s[nt][2] - mn1); rs1 += s[nt][2];
            s[nt][3] = __expf(s[nt][3] - mn1); rs1 += s[nt][3];
        }
        rs0 += __shfl_xor_sync(0xffffffffu, rs0, 1);
        rs0 += __shfl_xor_sync(0xffffffffu, rs0, 2);
        rs1 += __shfl_xor_sync(0xffffffffu, rs1, 1);
        rs1 += __shfl_xor_sync(0xffffffffu, rs1, 2);
        lrow0 = lrow0 * cor0 + rs0;
        lrow1 = lrow1 * cor1 + rs1;

#pragma unroll
        for (int nt = 0; nt < 8; nt++) {
            o[nt][0] *= cor0; o[nt][1] *= cor0;
            o[nt][2] *= cor1; o[nt][3] *= cor1;
        }

        // Store P (tf32) into QPs (warp-private rows)
        __syncwarp();   // prior PV reads of QPs complete
        {
            int rl = (w * 16 + g) * 72;
            int rh = rl + 8 * 72;
#pragma unroll
            for (int nt = 0; nt < 8; nt++) {
                *(float2*)&QPs[rl + nt * 8 + 2 * t] =
                    make_float2(tf32r(s[nt][0]), tf32r(s[nt][1]));
                *(float2*)&QPs[rh + nt * 8 + 2 * t] =
                    make_float2(tf32r(s[nt][2]), tf32r(s[nt][3]));
            }
        }
        __syncwarp();

        // O += P @ V
        {
            int rl = (w * 16 + g) * 72;
            int rh = rl + 8 * 72;
#pragma unroll
            for (int k8 = 0; k8 < 8; k8++) {
                unsigned pa0 = FU(QPs[rl + k8 * 8 + t]);
                unsigned pa1 = FU(QPs[rh + k8 * 8 + t]);
                unsigned pa2 = FU(QPs[rl + k8 * 8 + t + 4]);
                unsigned pa3 = FU(QPs[rh + k8 * 8 + t + 4]);
#pragma unroll
                for (int nt = 0; nt < 8; nt++) {
                    int vb = (k8 * 8 + t) * 72 + nt * 8 + g;
                    unsigned b0 = FU(Vs[vb]);
                    unsigned b1 = FU(Vs[vb + 4 * 72]);
                    mma8(o[nt][0], o[nt][1], o[nt][2], o[nt][3],
                         pa0, pa1, pa2, pa3, b0, b1);
                }
            }
        }
    }

    // Epilogue: normalize and write to g_O[b, n, h*64 + d]
    float inv0 = 1.0f / lrow0, inv1 = 1.0f / lrow1;
    float* Og = g_O + ((size_t)b * Nq + n0 + w * 16 + g) * INNERq + h * DHq;
#pragma unroll
    for (int nt = 0; nt < 8; nt++) {
        *(float2*)&Og[nt * 8 + 2 * t] =
            make_float2(o[nt][0] * inv0, o[nt][1] * inv0);
        *(float2*)&Og[(size_t)8 * INNERq + nt * 8 + 2 * t] =
            make_float2(o[nt][2] * inv1, o[nt][3] * inv1);
    }
}

// ---------------------------------------------------------------------------
// Kernel 4: output projection.  g_O[4096,512] @ W_out[512,512] + b_out -> out
// ---------------------------------------------------------------------------
__global__ void __launch_bounds__(256) out_proj_kernel(const float* __restrict__ Wout,
                                                       const float* __restrict__ bout,
                                                       float* __restrict__ out) {
    __shared__ float sA[128 * 20];
    __shared__ float sB[16 * 136];
    float c[16][4] = {};
    const int row0 = blockIdx.y * 128;
    const int col0 = blockIdx.x * 128;
    gemm128_tf32(g_O, INNERq, Wout, DIMq, row0, col0, INNERq, c, sA, sB);

    const int tid  = threadIdx.x;
    const int lane = tid & 31;
    const int w    = tid >> 5;
    const int wm   = w >> 2, wn = w & 3;
    const int g    = lane >> 2, t = lane & 3;

#pragma unroll
    for (int mt = 0; mt < 4; mt++) {
#pragma unroll
        for (int nt = 0; nt < 4; nt++) {
            int r  = row0 + wm * 64 + mt * 16 + g;
            int cc = col0 + wn * 32 + nt * 8 + 2 * t;
            float2 bb = *(const float2*)&bout[cc];
            *(float2*)&out[(size_t)r * DIMq + cc] =
                make_float2(c[mt * 4 + nt][0] + bb.x, c[mt * 4 + nt][1] + bb.y);
            *(float2*)&out[(size_t)(r + 8) * DIMq + cc] =
                make_float2(c[mt * 4 + nt][2] + bb.x, c[mt * 4 + nt][3] + bb.y);
        }
    }
}

// ---------------------------------------------------------------------------
extern "C" void kernel_launch(void* const* d_in, const int* in_sizes, int n_in,
                              void* d_out, int out_size) {
    const float* x    = (const float*)d_in[0];
    const float* x1   = (const float*)d_in[1];
    const float* am   = (const float*)d_in[2];
    const float* dp   = (const float*)d_in[3];
    const float* mp   = (const float*)d_in[4];
    const float* Wqv  = (const float*)d_in[5];
    const float* Wk   = (const float*)d_in[6];
    const float* Wout = (const float*)d_in[7];
    const float* bout = (const float*)d_in[8];
    float* out = (float*)d_out;

    cudaFuncSetAttribute(attn_kernel, cudaFuncAttributeMaxDynamicSharedMemorySize,
                         ATTN_SMEM_BYTES);

    proj_qv_kernel<<<dim3((2 * INNERq) / 128, 4096 / 128), 256>>>(x, Wqv);
    proj_k_kernel<<<dim3(INNERq / 128, 4096 / 128), 256>>>(x1, Wk);
    attn_kernel<<<dim3(Nq / 64, Hq, Bq), 128, ATTN_SMEM_BYTES>>>(am, dp, mp);
    out_proj_kernel<<<dim3(DIMq / 128, 4096 / 128), 256>>>(Wout, bout, out);
}